// round 6
// baseline (speedup 1.0000x reference)
#include <cuda_runtime.h>
#include <cstdint>

// idx = (x % 256) % 64 == x & 63 for x >= 0 (inputs randint [0,100000)).
// Output one-hot [B, 64] fp32 = 256 MB -> pure store-bandwidth problem.
//
// R3 changes vs R2:
//  - 1 thread = half a row (128B): ONE x load feeds FOUR independent
//    STG.256 -> max store MLP, 4x fewer LDGs (2M total).
//  - st.global.cs (streaming): 256MB write-once stream, evict-first in L2.
//  - 32-bit indexing, single bounds check, no per-store predication.

__device__ __forceinline__ void stg256cs(float* p,
                                         float a0, float a1, float a2, float a3,
                                         float a4, float a5, float a6, float a7) {
    asm volatile(
        "st.global.cs.v8.f32 [%0], {%1,%2,%3,%4,%5,%6,%7,%8};"
        :: "l"(p), "f"(a0), "f"(a1), "f"(a2), "f"(a3),
           "f"(a4), "f"(a5), "f"(a6), "f"(a7)
        : "memory");
}

__global__ __launch_bounds__(256)
void BasisEncoder_25890062860681_kernel(const int* __restrict__ x,
                                        float* __restrict__ out,
                                        unsigned n_half_rows) {
    unsigned t = blockIdx.x * blockDim.x + threadIdx.x;
    if (t >= n_half_rows) return;

    unsigned row  = t >> 1;
    unsigned half = t & 1;

    int idx  = x[row] & 63;              // (x % 256) % 64 for x >= 0
    int base = (int)(half << 5);         // 0 or 32

    float* p = out + (size_t)row * 64 + (half << 5);

    #pragma unroll
    for (int g = 0; g < 4; g++) {
        int b = base + (g << 3);
        float v0 = (idx == b + 0) ? 1.0f : 0.0f;
        float v1 = (idx == b + 1) ? 1.0f : 0.0f;
        float v2 = (idx == b + 2) ? 1.0f : 0.0f;
        float v3 = (idx == b + 3) ? 1.0f : 0.0f;
        float v4 = (idx == b + 4) ? 1.0f : 0.0f;
        float v5 = (idx == b + 5) ? 1.0f : 0.0f;
        float v6 = (idx == b + 6) ? 1.0f : 0.0f;
        float v7 = (idx == b + 7) ? 1.0f : 0.0f;
        stg256cs(p + (g << 3), v0, v1, v2, v3, v4, v5, v6, v7);
    }
}

extern "C" void kernel_launch(void* const* d_in, const int* in_sizes, int n_in,
                              void* d_out, int out_size) {
    const int* x = (const int*)d_in[0];
    float* out   = (float*)d_out;
    unsigned n_rows      = (unsigned)in_sizes[0];   // 1048576
    unsigned n_half_rows = n_rows * 2;              // 2M threads, 128B each

    int block = 256;
    unsigned grid = (n_half_rows + block - 1) / block;   // 8192 CTAs

    BasisEncoder_25890062860681_kernel<<<grid, block>>>(x, out, n_half_rows);
}